// round 4
// baseline (speedup 1.0000x reference)
#include <cuda_runtime.h>
#include <math.h>

#define B_ 4
#define N_ 2048
#define D_ 1024
#define E_ 8
#define BT_ 128
#define PAIRS (B_*E_)
#define TOK (B_*N_)

// ---------------- scratch (static __device__ globals; no allocs) ----------------
__device__ float g_h  [(size_t)PAIRS*N_*BT_];   // down-proj rows
__device__ float g_qb [(size_t)PAIRS*N_*BT_];
__device__ float g_kb [(size_t)PAIRS*N_*BT_];
__device__ float g_vb [(size_t)PAIRS*N_*BT_];
__device__ float g_ya [(size_t)PAIRS*N_*BT_];   // attention out rows
__device__ float g_yup[(size_t)PAIRS*N_*D_];    // up-proj rows (D=1024)
__device__ int   g_idx[PAIRS*N_];               // compacted token indices per (b,e)
__device__ int   g_cnt[PAIRS];
__device__ int   g_top2[TOK*2];
__device__ float g_topw[TOK*2];
__device__ float g_probs[TOK*E_];
__device__ int   g_prow[TOK*2];                 // inverse map: token -> packed row (or -1)

// ---------------- 1. router ----------------
__global__ void router_kernel(const float* __restrict__ x, const float* __restrict__ Wg){
    int tok = blockIdx.x;
    int tid = threadIdx.x;
    float a[E_];
    #pragma unroll
    for(int e=0;e<E_;e++) a[e]=0.f;
    const float* xr = x + (size_t)tok*D_;
    for(int d=tid; d<D_; d+=256){
        float xv = xr[d];
        const float* wg = Wg + d*E_;
        #pragma unroll
        for(int e=0;e<E_;e++) a[e] += xv*wg[e];
    }
    #pragma unroll
    for(int e=0;e<E_;e++)
        for(int off=16;off>0;off>>=1) a[e] += __shfl_down_sync(0xffffffffu,a[e],off);
    __shared__ float sm[8][E_];
    __shared__ float lg[E_];
    int w = tid>>5;
    if((tid&31)==0){ for(int e=0;e<E_;e++) sm[w][e]=a[e]; }
    __syncthreads();
    if(tid<E_){ float s=0.f; for(int w2=0;w2<8;w2++) s+=sm[w2][tid]; lg[tid]=s; }
    __syncthreads();
    if(tid==0){
        float mx=lg[0];
        #pragma unroll
        for(int e=1;e<E_;e++) mx=fmaxf(mx,lg[e]);
        float p[E_]; float s=0.f;
        #pragma unroll
        for(int e=0;e<E_;e++){ p[e]=__expf(lg[e]-mx); s+=p[e]; }
        float inv=1.f/s;
        #pragma unroll
        for(int e=0;e<E_;e++){ p[e]*=inv; g_probs[tok*E_+e]=p[e]; }
        int i0=0;
        #pragma unroll
        for(int e=1;e<E_;e++) if(p[e]>p[i0]) i0=e;
        int i1=(i0==0)?1:0;
        #pragma unroll
        for(int e=0;e<E_;e++){ if(e==i0) continue; if(p[e]>p[i1]) i1=e; }
        float ws=p[i0]+p[i1];
        g_top2[tok*2]=i0;  g_top2[tok*2+1]=i1;
        g_topw[tok*2]=p[i0]/ws; g_topw[tok*2+1]=p[i1]/ws;
        g_prow[tok*2]=-1;  g_prow[tok*2+1]=-1;
    }
}

// ---------------- 2. ordered compaction per (b,e) ----------------
// active_mask arrives as int32 (harness promotes bool -> int32)
__global__ void compact_kernel(const int* __restrict__ act){
    int pair=blockIdx.x; int b=pair>>3, e=pair&7;
    int tid=threadIdx.x, w=tid>>5, lane=tid&31;
    __shared__ int wcnt[8], woff[8], sbase;
    if(tid==0) sbase=0;
    __syncthreads();
    for(int c0=0;c0<N_;c0+=256){
        int n=c0+tid;
        int tok=b*N_+n;
        int i0=g_top2[tok*2], i1=g_top2[tok*2+1];
        int pred = (act[tok]!=0) && (i0==e || i1==e);
        unsigned bal=__ballot_sync(0xffffffffu,(unsigned)pred);
        int pre=__popc(bal & ((1u<<lane)-1u));
        if(lane==0) wcnt[w]=__popc(bal);
        __syncthreads();
        if(tid==0){
            int run=sbase;
            for(int w2=0;w2<8;w2++){ woff[w2]=run; run+=wcnt[w2]; }
            sbase=run;
        }
        __syncthreads();
        if(pred){
            int pos=woff[w]+pre;
            g_idx[pair*N_+pos]=n;
            int slot=(i0==e)?0:1;
            g_prow[tok*2+slot]=pair*N_+pos;
        }
        __syncthreads();
    }
    if(tid==0) g_cnt[pair]=sbase;
}

// ---------------- 3. down-proj: gathered x @ W_down[e]  (K=1024, N=128) ----------------
__global__ void down_kernel(const float* __restrict__ x, const float* __restrict__ Wd){
    int pair=blockIdx.x;
    int cnt=g_cnt[pair];
    int rb=blockIdx.y*64;
    if(rb>=cnt) return;
    int b=pair>>3, e=pair&7;
    const int* idx=g_idx+pair*N_;
    const float* W=Wd+(size_t)e*D_*BT_;
    __shared__ float As[64][33];
    __shared__ float Bs[32][BT_];
    int tid=threadIdx.x, tx=tid&15, ty=tid>>4;
    float acc[4][8];
    #pragma unroll
    for(int i=0;i<4;i++){
        #pragma unroll
        for(int j=0;j<8;j++) acc[i][j]=0.f;
    }
    for(int k0=0;k0<D_;k0+=32){
        for(int i=tid;i<64*32;i+=256){
            int r=i>>5, kk=i&31;
            int rr=rb+r; if(rr>=cnt) rr=cnt-1;
            int tok=idx[rr];
            As[r][kk]=x[((size_t)(b*N_+tok))*D_ + k0+kk];
        }
        for(int i=tid;i<32*BT_;i+=256){
            int kk=i>>7, c=i&127;
            Bs[kk][c]=W[(size_t)(k0+kk)*BT_ + c];
        }
        __syncthreads();
        #pragma unroll
        for(int kk=0;kk<32;kk++){
            float av[4], bv[8];
            #pragma unroll
            for(int i=0;i<4;i++) av[i]=As[ty+16*i][kk];
            #pragma unroll
            for(int j=0;j<8;j++) bv[j]=Bs[kk][tx+16*j];
            #pragma unroll
            for(int i=0;i<4;i++){
                #pragma unroll
                for(int j=0;j<8;j++) acc[i][j]+=av[i]*bv[j];
            }
        }
        __syncthreads();
    }
    size_t obase=(size_t)pair*N_;
    #pragma unroll
    for(int i=0;i<4;i++){
        int r=rb+ty+16*i;
        if(r<cnt){
            #pragma unroll
            for(int j=0;j<8;j++) g_h[(obase+r)*BT_ + tx+16*j]=acc[i][j];
        }
    }
}

// ---------------- 4. q/k/v: h @ W  (K=128, N=128), z selects which ----------------
__global__ void qkv_kernel(const float* __restrict__ Wq, const float* __restrict__ Wk,
                           const float* __restrict__ Wv){
    int pair=blockIdx.x;
    int cnt=g_cnt[pair];
    int rb=blockIdx.y*64;
    if(rb>=cnt) return;
    int e=pair&7;
    int which=blockIdx.z;
    const float* W=(which==0?Wq:(which==1?Wk:Wv))+(size_t)e*BT_*BT_;
    float* dst=(which==0?g_qb:(which==1?g_kb:g_vb));
    const float* A=g_h+(size_t)pair*N_*BT_;
    __shared__ float As[64][33];
    __shared__ float Bs[32][BT_];
    int tid=threadIdx.x, tx=tid&15, ty=tid>>4;
    float acc[4][8];
    #pragma unroll
    for(int i=0;i<4;i++){
        #pragma unroll
        for(int j=0;j<8;j++) acc[i][j]=0.f;
    }
    for(int k0=0;k0<BT_;k0+=32){
        for(int i=tid;i<64*32;i+=256){
            int r=i>>5, kk=i&31;
            int rr=rb+r; if(rr>=cnt) rr=cnt-1;
            As[r][kk]=A[(size_t)rr*BT_ + k0+kk];
        }
        for(int i=tid;i<32*BT_;i+=256){
            int kk=i>>7, c=i&127;
            Bs[kk][c]=W[(size_t)(k0+kk)*BT_ + c];
        }
        __syncthreads();
        #pragma unroll
        for(int kk=0;kk<32;kk++){
            float av[4], bv[8];
            #pragma unroll
            for(int i=0;i<4;i++) av[i]=As[ty+16*i][kk];
            #pragma unroll
            for(int j=0;j<8;j++) bv[j]=Bs[kk][tx+16*j];
            #pragma unroll
            for(int i=0;i<4;i++){
                #pragma unroll
                for(int j=0;j<8;j++) acc[i][j]+=av[i]*bv[j];
            }
        }
        __syncthreads();
    }
    size_t obase=(size_t)pair*N_;
    #pragma unroll
    for(int i=0;i<4;i++){
        int r=rb+ty+16*i;
        if(r<cnt){
            #pragma unroll
            for(int j=0;j<8;j++) dst[(obase+r)*BT_ + tx+16*j]=acc[i][j];
        }
    }
}

// ---------------- 5. causal attention over compacted rows ----------------
// 8 queries / block of 128 threads; thread t owns output dim t.
#define ATTN_SMEM ((128*129 + 8*128 + 8*128 + 32)*4)
__global__ void attn_kernel(){
    extern __shared__ float sm[];
    float* kv = sm;               // [128][129] padded tile (k, then v)
    float* qs = sm + 128*129;     // [8][128]
    float* ps = qs + 8*128;       // [8][128]
    float* red= ps + 8*128;       // [4+]
    int pair=blockIdx.x;
    int cnt=g_cnt[pair];
    int q0=blockIdx.y*8;
    if(q0>=cnt) return;
    int t=threadIdx.x, lane=t&31, w=t>>5;
    size_t base=(size_t)pair*N_;
    const float scale=0.08838834764831845f;  // 1/sqrt(128)
    #pragma unroll
    for(int q=0;q<8;q++){
        int r=q0+q; if(r>=cnt) r=cnt-1;
        qs[q*128+t]=g_qb[(base+r)*BT_+t]*scale;
    }
    __syncthreads();
    float m[8],l[8],acc[8];
    #pragma unroll
    for(int q=0;q<8;q++){ m[q]=-1e30f; l[q]=0.f; acc[q]=0.f; }
    int iqmax=min(q0+7,cnt-1);
    for(int kb=0;kb<=iqmax;kb+=128){
        for(int r=0;r<128;r++){
            int j=kb+r;
            kv[r*129+t]=(j<cnt)?g_kb[(base+j)*BT_+t]:0.f;
        }
        __syncthreads();
        float s[8];
        #pragma unroll
        for(int q=0;q<8;q++) s[q]=0.f;
        for(int d=0;d<128;d++){
            float kvv=kv[t*129+d];
            #pragma unroll
            for(int q=0;q<8;q++) s[q]+=qs[q*128+d]*kvv;
        }
        int j=kb+t;
        #pragma unroll
        for(int q=0;q<8;q++){
            int iq=q0+q;
            bool valid=(j<=iq)&&(j<cnt)&&(iq<cnt);
            float sv=valid?s[q]:-1e30f;
            float v=sv;
            for(int off=16;off>0;off>>=1) v=fmaxf(v,__shfl_xor_sync(0xffffffffu,v,off));
            if(lane==0) red[w]=v;
            __syncthreads();
            float mx=fmaxf(fmaxf(red[0],red[1]),fmaxf(red[2],red[3]));
            __syncthreads();
            float mn=fmaxf(m[q],mx);
            float p=valid?__expf(sv-mn):0.f;
            float corr=__expf(m[q]-mn);
            float vs=p;
            for(int off=16;off>0;off>>=1) vs+=__shfl_xor_sync(0xffffffffu,vs,off);
            if(lane==0) red[w]=vs;
            __syncthreads();
            float psum=red[0]+red[1]+red[2]+red[3];
            __syncthreads();
            l[q]=l[q]*corr+psum;
            acc[q]*=corr;
            m[q]=mn;
            ps[q*128+t]=p;
        }
        __syncthreads();
        for(int r=0;r<128;r++){
            int jj=kb+r;
            kv[r*129+t]=(jj<cnt)?g_vb[(base+jj)*BT_+t]:0.f;
        }
        __syncthreads();
        for(int r=0;r<128;r++){
            float vv=kv[r*129+t];
            #pragma unroll
            for(int q=0;q<8;q++) acc[q]+=ps[q*128+r]*vv;
        }
        __syncthreads();
    }
    #pragma unroll
    for(int q=0;q<8;q++){
        int iq=q0+q;
        if(iq<cnt) g_ya[(base+iq)*BT_+t]=acc[q]/l[q];
    }
}

// ---------------- 6. up-proj: y_attn @ W_up[e]  (K=128, N=1024 tiled by 128) ----------------
__global__ void up_kernel(const float* __restrict__ Wu){
    int pair=blockIdx.x;
    int cnt=g_cnt[pair];
    int rb=blockIdx.y*64;
    if(rb>=cnt) return;
    int e=pair&7;
    int c0=blockIdx.z*128;
    const float* W=Wu+(size_t)e*BT_*D_;
    const float* A=g_ya+(size_t)pair*N_*BT_;
    __shared__ float As[64][33];
    __shared__ float Bs[32][128];
    int tid=threadIdx.x, tx=tid&15, ty=tid>>4;
    float acc[4][8];
    #pragma unroll
    for(int i=0;i<4;i++){
        #pragma unroll
        for(int j=0;j<8;j++) acc[i][j]=0.f;
    }
    for(int k0=0;k0<BT_;k0+=32){
        for(int i=tid;i<64*32;i+=256){
            int r=i>>5, kk=i&31;
            int rr=rb+r; if(rr>=cnt) rr=cnt-1;
            As[r][kk]=A[(size_t)rr*BT_ + k0+kk];
        }
        for(int i=tid;i<32*128;i+=256){
            int kk=i>>7, c=i&127;
            Bs[kk][c]=W[(size_t)(k0+kk)*D_ + c0+c];
        }
        __syncthreads();
        #pragma unroll
        for(int kk=0;kk<32;kk++){
            float av[4], bv[8];
            #pragma unroll
            for(int i=0;i<4;i++) av[i]=As[ty+16*i][kk];
            #pragma unroll
            for(int j=0;j<8;j++) bv[j]=Bs[kk][tx+16*j];
            #pragma unroll
            for(int i=0;i<4;i++){
                #pragma unroll
                for(int j=0;j<8;j++) acc[i][j]+=av[i]*bv[j];
            }
        }
        __syncthreads();
    }
    size_t obase=(size_t)pair*N_;
    #pragma unroll
    for(int i=0;i<4;i++){
        int r=rb+ty+16*i;
        if(r<cnt){
            #pragma unroll
            for(int j=0;j<8;j++) g_yup[(obase+r)*D_ + c0+tx+16*j]=acc[i][j];
        }
    }
}

// ---------------- 7. combine: out = w0*y[r0] + w1*y[r1] ----------------
__global__ void combine_kernel(float* __restrict__ out){
    int tok=blockIdx.x;
    int r0=g_prow[tok*2], r1=g_prow[tok*2+1];
    float w0=g_topw[tok*2], w1=g_topw[tok*2+1];
    for(int d=threadIdx.x; d<D_; d+=256){
        float a=0.f;
        if(r0>=0) a+=w0*g_yup[(size_t)r0*D_+d];
        if(r1>=0) a+=w1*g_yup[(size_t)r1*D_+d];
        out[(size_t)tok*D_+d]=a;
    }
}

// ---------------- 8. loss + max_vio (deterministic tree reduction) ----------------
// top_k hardcoded to 2 (matches the hardcoded top-2 router above)
__global__ void loss_kernel(const int* __restrict__ act, float* __restrict__ out,
                            int out_size){
    int tid=threadIdx.x;
    float pm[E_];
    #pragma unroll
    for(int e=0;e<E_;e++) pm[e]=0.f;
    float asum=0.f;
    for(int t=tid;t<TOK;t+=256){
        float av=(act[t]!=0)?1.f:0.f;
        asum+=av;
        #pragma unroll
        for(int e=0;e<E_;e++) pm[e]+=g_probs[t*E_+e]*av;
    }
    __shared__ float buf[256];
    __shared__ float res[E_+1];
    for(int q=0;q<E_+1;q++){
        buf[tid]=(q<E_)?pm[q]:asum;
        __syncthreads();
        for(int s=128;s>0;s>>=1){ if(tid<s) buf[tid]+=buf[tid+s]; __syncthreads(); }
        if(tid==0) res[q]=buf[0];
        __syncthreads();
    }
    if(tid==0){
        const int topk=2;
        float denom=fmaxf(res[E_],1.f);
        float loss=0.f, mx=0.f;
        for(int e=0;e<E_;e++){
            int c=0;
            for(int b=0;b<B_;b++) c+=g_cnt[b*E_+e];
            float frac=(float)c/denom;
            loss+=frac*(res[e]/denom);
            if(frac>mx) mx=frac;
        }
        loss*=(float)E_/(float)topk;
        float vio=mx/((float)topk/(float)E_)-1.f;
        if(out_size>(int)((size_t)B_*N_*D_))   out[(size_t)B_*N_*D_]=loss;
        if(out_size>(int)((size_t)B_*N_*D_+1)) out[(size_t)B_*N_*D_+1]=vio;
    }
}

// ---------------- launch ----------------
extern "C" void kernel_launch(void* const* d_in, const int* in_sizes, int n_in,
                              void* d_out, int out_size){
    const float* x   =(const float*)d_in[0];
    const int*   pos =(const int*)d_in[1];           (void)pos;
    const int*   act =(const int*)d_in[2];           // bool promoted to int32 by harness
    const float* Wg  =(const float*)d_in[3];
    const float* Wd  =(const float*)d_in[4];
    const float* Wq  =(const float*)d_in[5];
    const float* Wk  =(const float*)d_in[6];
    const float* Wv  =(const float*)d_in[7];
    const float* Wu  =(const float*)d_in[8];
    (void)in_sizes; (void)n_in;
    float* out=(float*)d_out;

    cudaFuncSetAttribute(attn_kernel, cudaFuncAttributeMaxDynamicSharedMemorySize, ATTN_SMEM);

    router_kernel <<<TOK, 256>>>(x, Wg);
    compact_kernel<<<PAIRS, 256>>>(act);
    down_kernel   <<<dim3(PAIRS, N_/64), 256>>>(x, Wd);
    qkv_kernel    <<<dim3(PAIRS, N_/64, 3), 256>>>(Wq, Wk, Wv);
    attn_kernel   <<<dim3(PAIRS, N_/8), 128, ATTN_SMEM>>>();
    up_kernel     <<<dim3(PAIRS, N_/64, D_/128), 256>>>(Wu);
    combine_kernel<<<TOK, 256>>>(out);
    loss_kernel   <<<1, 256>>>(act, out, out_size);
}

// round 5
// speedup vs baseline: 1.3598x; 1.3598x over previous
#include <cuda_runtime.h>
#include <math.h>

#define B_ 4
#define N_ 2048
#define D_ 1024
#define E_ 8
#define BT_ 128
#define PAIRS (B_*E_)
#define TOK (B_*N_)

// ---------------- scratch (static __device__ globals; no allocs) ----------------
__device__ float g_h  [(size_t)PAIRS*N_*BT_];
__device__ float g_qb [(size_t)PAIRS*N_*BT_];
__device__ float g_kb [(size_t)PAIRS*N_*BT_];
__device__ float g_vb [(size_t)PAIRS*N_*BT_];
__device__ float g_ya [(size_t)PAIRS*N_*BT_];
__device__ float g_yup[(size_t)PAIRS*N_*D_];
__device__ int   g_idx[PAIRS*N_];
__device__ int   g_cnt[PAIRS];
__device__ int   g_top2[TOK*2];
__device__ float g_topw[TOK*2];
__device__ float g_probs[TOK*E_];
__device__ int   g_prow[TOK*2];

// ---------------- 1. router ----------------
__global__ void router_kernel(const float* __restrict__ x, const float* __restrict__ Wg){
    int tok = blockIdx.x;
    int tid = threadIdx.x;
    float a[E_];
    #pragma unroll
    for(int e=0;e<E_;e++) a[e]=0.f;
    const float* xr = x + (size_t)tok*D_;
    for(int d=tid; d<D_; d+=256){
        float xv = xr[d];
        const float* wg = Wg + d*E_;
        #pragma unroll
        for(int e=0;e<E_;e++) a[e] += xv*wg[e];
    }
    #pragma unroll
    for(int e=0;e<E_;e++)
        for(int off=16;off>0;off>>=1) a[e] += __shfl_down_sync(0xffffffffu,a[e],off);
    __shared__ float sm[8][E_];
    __shared__ float lg[E_];
    int w = tid>>5;
    if((tid&31)==0){ for(int e=0;e<E_;e++) sm[w][e]=a[e]; }
    __syncthreads();
    if(tid<E_){ float s=0.f; for(int w2=0;w2<8;w2++) s+=sm[w2][tid]; lg[tid]=s; }
    __syncthreads();
    if(tid==0){
        float mx=lg[0];
        #pragma unroll
        for(int e=1;e<E_;e++) mx=fmaxf(mx,lg[e]);
        float p[E_]; float s=0.f;
        #pragma unroll
        for(int e=0;e<E_;e++){ p[e]=__expf(lg[e]-mx); s+=p[e]; }
        float inv=1.f/s;
        #pragma unroll
        for(int e=0;e<E_;e++){ p[e]*=inv; g_probs[tok*E_+e]=p[e]; }
        int i0=0;
        #pragma unroll
        for(int e=1;e<E_;e++) if(p[e]>p[i0]) i0=e;
        int i1=(i0==0)?1:0;
        #pragma unroll
        for(int e=0;e<E_;e++){ if(e==i0) continue; if(p[e]>p[i1]) i1=e; }
        float ws=p[i0]+p[i1];
        g_top2[tok*2]=i0;  g_top2[tok*2+1]=i1;
        g_topw[tok*2]=p[i0]/ws; g_topw[tok*2+1]=p[i1]/ws;
        g_prow[tok*2]=-1;  g_prow[tok*2+1]=-1;
    }
}

// ---------------- 2. ordered compaction per (b,e) ----------------
__global__ void compact_kernel(const int* __restrict__ act){
    int pair=blockIdx.x; int b=pair>>3, e=pair&7;
    int tid=threadIdx.x, w=tid>>5, lane=tid&31;
    __shared__ int wcnt[8], woff[8], sbase;
    if(tid==0) sbase=0;
    __syncthreads();
    for(int c0=0;c0<N_;c0+=256){
        int n=c0+tid;
        int tok=b*N_+n;
        int i0=g_top2[tok*2], i1=g_top2[tok*2+1];
        int pred = (act[tok]!=0) && (i0==e || i1==e);
        unsigned bal=__ballot_sync(0xffffffffu,(unsigned)pred);
        int pre=__popc(bal & ((1u<<lane)-1u));
        if(lane==0) wcnt[w]=__popc(bal);
        __syncthreads();
        if(tid==0){
            int run=sbase;
            for(int w2=0;w2<8;w2++){ woff[w2]=run; run+=wcnt[w2]; }
            sbase=run;
        }
        __syncthreads();
        if(pred){
            int pos=woff[w]+pre;
            g_idx[pair*N_+pos]=n;
            int slot=(i0==e)?0:1;
            g_prow[tok*2+slot]=pair*N_+pos;
        }
        __syncthreads();
    }
    if(tid==0) g_cnt[pair]=sbase;
}

// ============ GEMM microtile: 128x128 block tile, 256 threads, 8x8 per thread ============

// ---------------- 3. down-proj: gathered x @ W_down[e]  (K=1024, N=128) ----------------
__global__ __launch_bounds__(256) void down_kernel(const float* __restrict__ x,
                                                   const float* __restrict__ Wd){
    int pair=blockIdx.x;
    int cnt=g_cnt[pair];
    int rb=blockIdx.y*128;
    if(rb>=cnt) return;
    int b=pair>>3, e=pair&7;
    const int* idx=g_idx+pair*N_;
    const float* W=Wd+(size_t)e*D_*BT_;
    __shared__ float As[128*20];   // [row][kk] pad 20
    __shared__ float Bs[16*132];   // [kk][col] pad 132
    int tid=threadIdx.x, tx=tid&15, ty=tid>>4;
    // A gather pointers: 2 tasks/thread, (row=j>>2, kg=j&3)
    const float* aptr[2]; int arow[2], akg[2];
    #pragma unroll
    for(int s=0;s<2;s++){
        int j=tid+s*256;
        arow[s]=j>>2; akg[s]=j&3;
        int rr=rb+arow[s]; if(rr>=cnt) rr=cnt-1;
        aptr[s]=x+((size_t)(b*N_+idx[rr]))*D_;
    }
    float acc[8][8];
    #pragma unroll
    for(int i=0;i<8;i++){
        #pragma unroll
        for(int j=0;j<8;j++) acc[i][j]=0.f;
    }
    for(int k0=0;k0<D_;k0+=16){
        __syncthreads();
        #pragma unroll
        for(int s=0;s<2;s++){
            float4 v=*(const float4*)(aptr[s]+k0+akg[s]*4);
            *(float4*)(&As[arow[s]*20+akg[s]*4])=v;
        }
        #pragma unroll
        for(int s=0;s<2;s++){
            int j=tid+s*256; int kk=j>>5, c4=j&31;
            float4 v=*(const float4*)(W+(size_t)(k0+kk)*BT_+c4*4);
            *(float4*)(&Bs[kk*132+c4*4])=v;
        }
        __syncthreads();
        #pragma unroll
        for(int kk=0;kk<16;kk++){
            float4 b0=*(const float4*)(&Bs[kk*132+tx*8]);
            float4 b1=*(const float4*)(&Bs[kk*132+tx*8+4]);
            float bv[8]={b0.x,b0.y,b0.z,b0.w,b1.x,b1.y,b1.z,b1.w};
            float av[8];
            #pragma unroll
            for(int i=0;i<8;i++) av[i]=As[(ty*8+i)*20+kk];
            #pragma unroll
            for(int i=0;i<8;i++){
                #pragma unroll
                for(int j=0;j<8;j++) acc[i][j]+=av[i]*bv[j];
            }
        }
    }
    size_t obase=(size_t)pair*N_;
    #pragma unroll
    for(int i=0;i<8;i++){
        int r=rb+ty*8+i;
        if(r<cnt){
            float4 o0={acc[i][0],acc[i][1],acc[i][2],acc[i][3]};
            float4 o1={acc[i][4],acc[i][5],acc[i][6],acc[i][7]};
            *(float4*)(&g_h[(obase+r)*BT_+tx*8])=o0;
            *(float4*)(&g_h[(obase+r)*BT_+tx*8+4])=o1;
        }
    }
}

// ---------------- 4. q/k/v merged: h @ {Wq,Wk,Wv}  (K=128, N=128) ----------------
// Full A tile (128x128) resident in smem; reused for all three weight matrices.
#define QKV_SMEM ((128*132 + 16*132)*4)
__global__ __launch_bounds__(256) void qkv_kernel(const float* __restrict__ Wq,
                                                  const float* __restrict__ Wk,
                                                  const float* __restrict__ Wv){
    int pair=blockIdx.x;
    int cnt=g_cnt[pair];
    int rb=blockIdx.y*128;
    if(rb>=cnt) return;
    int e=pair&7;
    extern __shared__ float smq[];
    float* As=smq;              // [128][132] row-major
    float* Bs=smq+128*132;      // [16][132]
    const float* A=g_h+(size_t)pair*N_*BT_;
    int tid=threadIdx.x, tx=tid&15, ty=tid>>4;
    // load full A tile (16 tasks: row=j>>5, dg=j&31)
    #pragma unroll
    for(int s=0;s<16;s++){
        int j=tid+s*256; int row=j>>5, dg=j&31;
        int rr=rb+row; if(rr>=cnt) rr=cnt-1;
        float4 v=*(const float4*)(A+(size_t)rr*BT_+dg*4);
        *(float4*)(&As[row*132+dg*4])=v;
    }
    size_t obase=(size_t)pair*N_;
    for(int which=0;which<3;which++){
        const float* W=(which==0?Wq:(which==1?Wk:Wv))+(size_t)e*BT_*BT_;
        float* dst=(which==0?g_qb:(which==1?g_kb:g_vb));
        float acc[8][8];
        #pragma unroll
        for(int i=0;i<8;i++){
            #pragma unroll
            for(int j=0;j<8;j++) acc[i][j]=0.f;
        }
        for(int k0=0;k0<BT_;k0+=16){
            __syncthreads();
            #pragma unroll
            for(int s=0;s<2;s++){
                int j=tid+s*256; int kk=j>>5, c4=j&31;
                float4 v=*(const float4*)(W+(size_t)(k0+kk)*BT_+c4*4);
                *(float4*)(&Bs[kk*132+c4*4])=v;
            }
            __syncthreads();
            #pragma unroll
            for(int kk=0;kk<16;kk++){
                float4 b0=*(const float4*)(&Bs[kk*132+tx*8]);
                float4 b1=*(const float4*)(&Bs[kk*132+tx*8+4]);
                float bv[8]={b0.x,b0.y,b0.z,b0.w,b1.x,b1.y,b1.z,b1.w};
                float av[8];
                #pragma unroll
                for(int i=0;i<8;i++) av[i]=As[(ty*8+i)*132+k0+kk];
                #pragma unroll
                for(int i=0;i<8;i++){
                    #pragma unroll
                    for(int j=0;j<8;j++) acc[i][j]+=av[i]*bv[j];
                }
            }
        }
        #pragma unroll
        for(int i=0;i<8;i++){
            int r=rb+ty*8+i;
            if(r<cnt){
                float4 o0={acc[i][0],acc[i][1],acc[i][2],acc[i][3]};
                float4 o1={acc[i][4],acc[i][5],acc[i][6],acc[i][7]};
                *(float4*)(&dst[(obase+r)*BT_+tx*8])=o0;
                *(float4*)(&dst[(obase+r)*BT_+tx*8+4])=o1;
            }
        }
    }
}

// ---------------- 5. attention: 32 q/block, warp owns 4 queries, shuffle softmax ----------------
// smem: Kt[128][128] d-major XOR-swizzled, Vs[128][132], Qt[128][36] d-major, Ps[32][132]
#define ATTN_SMEM ((128*128 + 128*132 + 128*36 + 32*132)*4)
__global__ __launch_bounds__(256) void attn_kernel(){
    extern __shared__ float sm[];
    float* Kt=sm;
    float* Vs=Kt+128*128;
    float* Qt=Vs+128*132;
    float* Ps=Qt+128*36;
    int pair=blockIdx.x;
    int cnt=g_cnt[pair];
    int q0=blockIdx.y*32;
    if(q0>=cnt) return;
    int t=threadIdx.x, lane=t&31, wy=t>>5;     // wy 0..7 -> queries wy*4..+3
    size_t base=(size_t)pair*N_;
    const float scale=0.08838834764831845f;
    // load Q transposed: Qt[d][q]
    #pragma unroll
    for(int s=0;s<4;s++){
        int j=t+s*256; int q=j>>5, dg=j&31;
        int r=q0+q; if(r>=cnt) r=cnt-1;
        float4 v=*(const float4*)(g_qb+(base+r)*BT_+dg*4);
        Qt[(dg*4+0)*36+q]=v.x*scale;
        Qt[(dg*4+1)*36+q]=v.y*scale;
        Qt[(dg*4+2)*36+q]=v.z*scale;
        Qt[(dg*4+3)*36+q]=v.w*scale;
    }
    float m[4],l[4],acc[4][4];
    #pragma unroll
    for(int i=0;i<4;i++){
        m[i]=-1e30f; l[i]=0.f;
        #pragma unroll
        for(int j=0;j<4;j++) acc[i][j]=0.f;
    }
    int iqmax=min(q0+31,cnt-1);
    for(int kb=0;kb<=iqmax;kb+=128){
        __syncthreads();   // Qt visible (1st iter) + protect Kt/Vs from prior consumers
        #pragma unroll
        for(int s=0;s<16;s++){
            int j=t+s*256; int key=j>>5, dg=j&31;
            int kg=kb+key;
            float4 kv4,vv4;
            if(kg<cnt){
                kv4=*(const float4*)(g_kb+(base+kg)*BT_+dg*4);
                vv4=*(const float4*)(g_vb+(base+kg)*BT_+dg*4);
            } else {
                kv4=make_float4(0.f,0.f,0.f,0.f); vv4=kv4;
            }
            *(float4*)(&Vs[key*132+dg*4])=vv4;
            int col=key^(4*dg);                 // XOR swizzle (dg = d>>2)
            Kt[(dg*4+0)*128+col]=kv4.x;
            Kt[(dg*4+1)*128+col]=kv4.y;
            Kt[(dg*4+2)*128+col]=kv4.z;
            Kt[(dg*4+3)*128+col]=kv4.w;
        }
        __syncthreads();
        // QK: s4[4 q][4 keys], keys = lane*4..+3
        float s4[4][4];
        #pragma unroll
        for(int i=0;i<4;i++){
            #pragma unroll
            for(int j=0;j<4;j++) s4[i][j]=0.f;
        }
        #pragma unroll 4
        for(int d=0;d<128;d++){
            float4 qv=*(const float4*)(&Qt[d*36+wy*4]);
            float4 kv=*(const float4*)(&Kt[d*128+4*(lane^(d>>2))]);
            s4[0][0]+=qv.x*kv.x; s4[0][1]+=qv.x*kv.y; s4[0][2]+=qv.x*kv.z; s4[0][3]+=qv.x*kv.w;
            s4[1][0]+=qv.y*kv.x; s4[1][1]+=qv.y*kv.y; s4[1][2]+=qv.y*kv.z; s4[1][3]+=qv.y*kv.w;
            s4[2][0]+=qv.z*kv.x; s4[2][1]+=qv.z*kv.y; s4[2][2]+=qv.z*kv.z; s4[2][3]+=qv.z*kv.w;
            s4[3][0]+=qv.w*kv.x; s4[3][1]+=qv.w*kv.y; s4[3][2]+=qv.w*kv.z; s4[3][3]+=qv.w*kv.w;
        }
        // online softmax per query (pure warp shuffles)
        #pragma unroll
        for(int i=0;i<4;i++){
            int iq=q0+wy*4+i;
            float p[4]; float tm=-1e30f;
            #pragma unroll
            for(int j=0;j<4;j++){
                int kg=kb+lane*4+j;
                bool valid=(kg<=iq)&&(kg<cnt)&&(iq<cnt);
                p[j]=valid?s4[i][j]:-1e30f;
                tm=fmaxf(tm,p[j]);
            }
            #pragma unroll
            for(int off=16;off>0;off>>=1) tm=fmaxf(tm,__shfl_xor_sync(0xffffffffu,tm,off));
            float mn=fmaxf(m[i],tm);
            float ps=0.f;
            #pragma unroll
            for(int j=0;j<4;j++){
                int kg=kb+lane*4+j;
                bool valid=(kg<=iq)&&(kg<cnt)&&(iq<cnt);
                p[j]=valid?__expf(p[j]-mn):0.f;
                ps+=p[j];
            }
            #pragma unroll
            for(int off=16;off>0;off>>=1) ps+=__shfl_xor_sync(0xffffffffu,ps,off);
            float corr=__expf(m[i]-mn);
            l[i]=l[i]*corr+ps;
            m[i]=mn;
            #pragma unroll
            for(int j=0;j<4;j++) acc[i][j]*=corr;
            float4 pv={p[0],p[1],p[2],p[3]};
            *(float4*)(&Ps[(wy*4+i)*132+lane*4])=pv;   // own-warp rows only
        }
        __syncwarp();
        // AV: acc[4 q][4 d], d = lane*4..+3
        #pragma unroll 4
        for(int key=0;key<128;key++){
            float4 vv=*(const float4*)(&Vs[key*132+lane*4]);
            float p0=Ps[(wy*4+0)*132+key];
            float p1=Ps[(wy*4+1)*132+key];
            float p2=Ps[(wy*4+2)*132+key];
            float p3=Ps[(wy*4+3)*132+key];
            acc[0][0]+=p0*vv.x; acc[0][1]+=p0*vv.y; acc[0][2]+=p0*vv.z; acc[0][3]+=p0*vv.w;
            acc[1][0]+=p1*vv.x; acc[1][1]+=p1*vv.y; acc[1][2]+=p1*vv.z; acc[1][3]+=p1*vv.w;
            acc[2][0]+=p2*vv.x; acc[2][1]+=p2*vv.y; acc[2][2]+=p2*vv.z; acc[2][3]+=p2*vv.w;
            acc[3][0]+=p3*vv.x; acc[3][1]+=p3*vv.y; acc[3][2]+=p3*vv.z; acc[3][3]+=p3*vv.w;
        }
        __syncwarp();
    }
    #pragma unroll
    for(int i=0;i<4;i++){
        int iq=q0+wy*4+i;
        if(iq<cnt){
            float inv=1.f/l[i];
            float4 o={acc[i][0]*inv,acc[i][1]*inv,acc[i][2]*inv,acc[i][3]*inv};
            *(float4*)(&g_ya[(base+iq)*BT_+lane*4])=o;
        }
    }
}

// ---------------- 6. up-proj: y_attn @ W_up[e]  (K=128, N=1024 tiled by 128) ----------------
#define UP_SMEM ((128*132 + 16*132)*4)
__global__ __launch_bounds__(256) void up_kernel(const float* __restrict__ Wu){
    int pair=blockIdx.x;
    int cnt=g_cnt[pair];
    int rb=blockIdx.y*128;
    if(rb>=cnt) return;
    int e=pair&7;
    int c0=blockIdx.z*128;
    extern __shared__ float smu[];
    float* As=smu;              // [128][132]
    float* Bs=smu+128*132;      // [16][132]
    const float* W=Wu+(size_t)e*BT_*D_;
    const float* A=g_ya+(size_t)pair*N_*BT_;
    int tid=threadIdx.x, tx=tid&15, ty=tid>>4;
    #pragma unroll
    for(int s=0;s<16;s++){
        int j=tid+s*256; int row=j>>5, dg=j&31;
        int rr=rb+row; if(rr>=cnt) rr=cnt-1;
        float4 v=*(const float4*)(A+(size_t)rr*BT_+dg*4);
        *(float4*)(&As[row*132+dg*4])=v;
    }
    float acc[8][8];
    #pragma unroll
    for(int i=0;i<8;i++){
        #pragma unroll
        for(int j=0;j<8;j++) acc[i][j]=0.f;
    }
    for(int k0=0;k0<BT_;k0+=16){
        __syncthreads();
        #pragma unroll
        for(int s=0;s<2;s++){
            int j=tid+s*256; int kk=j>>5, c4=j&31;
            float4 v=*(const float4*)(W+(size_t)(k0+kk)*D_+c0+c4*4);
            *(float4*)(&Bs[kk*132+c4*4])=v;
        }
        __syncthreads();
        #pragma unroll
        for(int kk=0;kk<16;kk++){
            float4 b0=*(const float4*)(&Bs[kk*132+tx*8]);
            float4 b1=*(const float4*)(&Bs[kk*132+tx*8+4]);
            float bv[8]={b0.x,b0.y,b0.z,b0.w,b1.x,b1.y,b1.z,b1.w};
            float av[8];
            #pragma unroll
            for(int i=0;i<8;i++) av[i]=As[(ty*8+i)*132+k0+kk];
            #pragma unroll
            for(int i=0;i<8;i++){
                #pragma unroll
                for(int j=0;j<8;j++) acc[i][j]+=av[i]*bv[j];
            }
        }
    }
    size_t obase=(size_t)pair*N_;
    #pragma unroll
    for(int i=0;i<8;i++){
        int r=rb+ty*8+i;
        if(r<cnt){
            float4 o0={acc[i][0],acc[i][1],acc[i][2],acc[i][3]};
            float4 o1={acc[i][4],acc[i][5],acc[i][6],acc[i][7]};
            *(float4*)(&g_yup[(obase+r)*D_+c0+tx*8])=o0;
            *(float4*)(&g_yup[(obase+r)*D_+c0+tx*8+4])=o1;
        }
    }
}

// ---------------- 7. combine (float4) ----------------
__global__ void combine_kernel(float* __restrict__ out){
    int tok=blockIdx.x;
    int r0=g_prow[tok*2], r1=g_prow[tok*2+1];
    float w0=g_topw[tok*2], w1=g_topw[tok*2+1];
    int d4=threadIdx.x;   // 256 threads x float4 = 1024
    float4 a={0.f,0.f,0.f,0.f};
    if(r0>=0){
        float4 y=*(const float4*)(&g_yup[(size_t)r0*D_+d4*4]);
        a.x+=w0*y.x; a.y+=w0*y.y; a.z+=w0*y.z; a.w+=w0*y.w;
    }
    if(r1>=0){
        float4 y=*(const float4*)(&g_yup[(size_t)r1*D_+d4*4]);
        a.x+=w1*y.x; a.y+=w1*y.y; a.z+=w1*y.z; a.w+=w1*y.w;
    }
    *(float4*)(&out[(size_t)tok*D_+d4*4])=a;
}

// ---------------- 8. loss + max_vio ----------------
__global__ void loss_kernel(const int* __restrict__ act, float* __restrict__ out,
                            int out_size){
    int tid=threadIdx.x;
    float pm[E_];
    #pragma unroll
    for(int e=0;e<E_;e++) pm[e]=0.f;
    float asum=0.f;
    for(int t=tid;t<TOK;t+=256){
        float av=(act[t]!=0)?1.f:0.f;
        asum+=av;
        #pragma unroll
        for(int e=0;e<E_;e++) pm[e]+=g_probs[t*E_+e]*av;
    }
    __shared__ float buf[256];
    __shared__ float res[E_+1];
    for(int q=0;q<E_+1;q++){
        buf[tid]=(q<E_)?pm[q]:asum;
        __syncthreads();
        for(int s=128;s>0;s>>=1){ if(tid<s) buf[tid]+=buf[tid+s]; __syncthreads(); }
        if(tid==0) res[q]=buf[0];
        __syncthreads();
    }
    if(tid==0){
        const int topk=2;
        float denom=fmaxf(res[E_],1.f);
        float loss=0.f, mx=0.f;
        for(int e=0;e<E_;e++){
            int c=0;
            for(int b=0;b<B_;b++) c+=g_cnt[b*E_+e];
            float frac=(float)c/denom;
            loss+=frac*(res[e]/denom);
            if(frac>mx) mx=frac;
        }
        loss*=(float)E_/(float)topk;
        float vio=mx/((float)topk/(float)E_)-1.f;
        if(out_size>(int)((size_t)B_*N_*D_))   out[(size_t)B_*N_*D_]=loss;
        if(out_size>(int)((size_t)B_*N_*D_+1)) out[(size_t)B_*N_*D_+1]=vio;
    }
}

// ---------------- launch ----------------
extern "C" void kernel_launch(void* const* d_in, const int* in_sizes, int n_in,
                              void* d_out, int out_size){
    const float* x   =(const float*)d_in[0];
    const int*   pos =(const int*)d_in[1];           (void)pos;
    const int*   act =(const int*)d_in[2];
    const float* Wg  =(const float*)d_in[3];
    const float* Wd  =(const float*)d_in[4];
    const float* Wq  =(const float*)d_in[5];
    const float* Wk  =(const float*)d_in[6];
    const float* Wv  =(const float*)d_in[7];
    const float* Wu  =(const float*)d_in[8];
    (void)in_sizes; (void)n_in;
    float* out=(float*)d_out;

    cudaFuncSetAttribute(qkv_kernel,  cudaFuncAttributeMaxDynamicSharedMemorySize, QKV_SMEM);
    cudaFuncSetAttribute(up_kernel,   cudaFuncAttributeMaxDynamicSharedMemorySize, UP_SMEM);
    cudaFuncSetAttribute(attn_kernel, cudaFuncAttributeMaxDynamicSharedMemorySize, ATTN_SMEM);

    router_kernel <<<TOK, 256>>>(x, Wg);
    compact_kernel<<<PAIRS, 256>>>(act);
    down_kernel   <<<dim3(PAIRS, N_/128), 256>>>(x, Wd);
    qkv_kernel    <<<dim3(PAIRS, N_/128), 256, QKV_SMEM>>>(Wq, Wk, Wv);
    attn_kernel   <<<dim3(PAIRS, N_/32), 256, ATTN_SMEM>>>();
    up_kernel     <<<dim3(PAIRS, N_/128, D_/128), 256, UP_SMEM>>>(Wu);
    combine_kernel<<<TOK, 256>>>(out);
    loss_kernel   <<<1, 256>>>(act, out, out_size);
}